// round 4
// baseline (speedup 1.0000x reference)
#include <cuda_runtime.h>
#include <cuda_bf16.h>
#include <math.h>

// ---------------- device scratch (no allocations allowed) ----------------
#define MAXN 100000
#define MAXE 3400000
#define MAXB 128

__device__ int   g_cnt[MAXN];
__device__ int   g_rowptr[MAXN + 1];
__device__ int   g_wtmp[MAXN];
__device__ int   g_col[MAXE];
__device__ int   g_part[MAXB];
__device__ int   g_partoff[MAXB];
__device__ float g_dinv[MAXN];
__device__ float g_z[MAXN * 16];
__device__ float g_h[MAXN * 16];
__device__ float g_u[MAXN * 8];

// packed f32x2 helpers (sm_103a)
#define FMA_F32X2(d, a, b, c) \
    asm("fma.rn.f32x2 %0, %1, %2, %3;" : "=l"(d) : "l"(a), "l"(b), "l"(c))
#define PACK_F32X2(p, lo, hi) \
    asm("mov.b64 %0, {%1, %2};" : "=l"(p) : "f"(lo), "f"(hi))
#define UNPACK_F32X2(lo, hi, p) \
    asm("mov.b64 {%0, %1}, %2;" : "=f"(lo), "=f"(hi) : "l"(p))

// ---------------- CSR build ----------------
__global__ void zero_cnt_k(int N) {
    int i = blockIdx.x * blockDim.x + threadIdx.x;
    if (i < N) g_cnt[i] = 0;
}

__global__ void count_k(const int* __restrict__ ei, int E, int N) {
    int base = (blockIdx.x * blockDim.x + threadIdx.x) * 4;
    const int* dstp = ei + E;
    if (base + 3 < E) {
        int4 d4 = *(const int4*)&dstp[base];
        if ((unsigned)d4.x < (unsigned)N) atomicAdd(&g_cnt[d4.x], 1);
        if ((unsigned)d4.y < (unsigned)N) atomicAdd(&g_cnt[d4.y], 1);
        if ((unsigned)d4.z < (unsigned)N) atomicAdd(&g_cnt[d4.z], 1);
        if ((unsigned)d4.w < (unsigned)N) atomicAdd(&g_cnt[d4.w], 1);
    } else {
        for (int e = base; e < E; ++e) {
            int d = dstp[e];
            if ((unsigned)d < (unsigned)N) atomicAdd(&g_cnt[d], 1);
        }
    }
}

__global__ void partial_k(int N) {
    __shared__ int red[32];
    int tid = threadIdx.x;
    int lane = tid & 31, wid = tid >> 5;
    int i = blockIdx.x * 1024 + tid;
    int v = (i < N) ? g_cnt[i] : 0;
#pragma unroll
    for (int off = 16; off > 0; off >>= 1) v += __shfl_xor_sync(0xFFFFFFFFu, v, off);
    if (lane == 0) red[wid] = v;
    __syncthreads();
    if (wid == 0) {
        int s = red[lane];
#pragma unroll
        for (int off = 16; off > 0; off >>= 1) s += __shfl_xor_sync(0xFFFFFFFFu, s, off);
        if (lane == 0) g_part[blockIdx.x] = s;
    }
}

__global__ void scanpart_k(int nb, int N) {
    __shared__ int sp[128];
    int t = threadIdx.x;
    int v = (t < nb) ? g_part[t] : 0;
    sp[t] = v;
    __syncthreads();
    for (int off = 1; off < 128; off <<= 1) {
        int a = (t >= off) ? sp[t - off] : 0;
        __syncthreads();
        sp[t] += a;
        __syncthreads();
    }
    if (t < nb) g_partoff[t] = sp[t] - v;
    if (t == nb - 1) g_rowptr[N] = sp[t];
}

__global__ void emit_k(int N) {
    __shared__ int wsums[32];
    int tid = threadIdx.x;
    int lane = tid & 31, wid = tid >> 5;
    int i = blockIdx.x * 1024 + tid;
    int c = (i < N) ? g_cnt[i] : 0;
    int v = c;
#pragma unroll
    for (int off = 1; off < 32; off <<= 1) {
        int t = __shfl_up_sync(0xFFFFFFFFu, v, off);
        if (lane >= off) v += t;
    }
    if (lane == 31) wsums[wid] = v;
    __syncthreads();
    if (wid == 0) {
        int w = wsums[lane];
#pragma unroll
        for (int off = 1; off < 32; off <<= 1) {
            int t = __shfl_up_sync(0xFFFFFFFFu, w, off);
            if (lane >= off) w += t;
        }
        wsums[lane] = w;
    }
    __syncthreads();
    int add = (wid > 0) ? wsums[wid - 1] : 0;
    int excl = v - c + add + g_partoff[blockIdx.x];
    if (i < N) {
        g_rowptr[i] = excl;
        g_wtmp[i]   = excl;
        g_dinv[i]   = rsqrtf((float)(c + 1));
    }
}

__global__ void scatter_k(const int* __restrict__ ei, int E, int N) {
    int base = (blockIdx.x * blockDim.x + threadIdx.x) * 4;
    const int* dstp = ei + E;
    if (base + 3 < E) {
        int4 s4 = *(const int4*)&ei[base];
        int4 d4 = *(const int4*)&dstp[base];
        if ((unsigned)d4.x < (unsigned)N && (unsigned)s4.x < (unsigned)N)
            g_col[atomicAdd(&g_wtmp[d4.x], 1)] = s4.x;
        if ((unsigned)d4.y < (unsigned)N && (unsigned)s4.y < (unsigned)N)
            g_col[atomicAdd(&g_wtmp[d4.y], 1)] = s4.y;
        if ((unsigned)d4.z < (unsigned)N && (unsigned)s4.z < (unsigned)N)
            g_col[atomicAdd(&g_wtmp[d4.z], 1)] = s4.z;
        if ((unsigned)d4.w < (unsigned)N && (unsigned)s4.w < (unsigned)N)
            g_col[atomicAdd(&g_wtmp[d4.w], 1)] = s4.w;
    } else {
        for (int e = base; e < E; ++e) {
            int s = ei[e], d = dstp[e];
            if ((unsigned)d < (unsigned)N && (unsigned)s < (unsigned)N)
                g_col[atomicAdd(&g_wtmp[d], 1)] = s;
        }
    }
}

// ---------------- GEMM1: z = dinv * (x @ W1)  [N,512]x[512,16] ----------------
// 2 nodes per thread, f32x2 packed accumulators (8 pairs per node),
// W row LDS amortized over both nodes. FMA2-pipe bound.
__global__ void __launch_bounds__(128) gemm1_k(const float* __restrict__ x,
                                               const float* __restrict__ W1, int N) {
    __shared__ ulonglong2 Ws[512 * 4];   // [k][quad]: 4 x 16B per row = 32 KB
    int tid = threadIdx.x;
    {
        const float4* Wg4 = (const float4*)W1;
        float4* Wsf = (float4*)Ws;
        for (int i = tid; i < 2048; i += 128) Wsf[i] = Wg4[i];
    }
    __syncthreads();

    int n0 = blockIdx.x * 256 + tid;       // always < N for this grid
    int n1 = n0 + 128;
    int n1c = (n1 < N) ? n1 : (N - 1);     // clamp for loads; store guarded

    const float4* xr0 = (const float4*)(x + (size_t)n0 * 512);
    const float4* xr1 = (const float4*)(x + (size_t)n1c * 512);

    unsigned long long a0[8], a1[8];
#pragma unroll
    for (int p = 0; p < 8; ++p) { a0[p] = 0ull; a1[p] = 0ull; }

#pragma unroll 2
    for (int k4 = 0; k4 < 128; ++k4) {
        float4 xv0 = xr0[k4];
        float4 xv1 = xr1[k4];
#pragma unroll
        for (int j = 0; j < 4; ++j) {
            float x0 = (j == 0) ? xv0.x : (j == 1) ? xv0.y : (j == 2) ? xv0.z : xv0.w;
            float x1 = (j == 0) ? xv1.x : (j == 1) ? xv1.y : (j == 2) ? xv1.z : xv1.w;
            unsigned long long p0, p1;
            PACK_F32X2(p0, x0, x0);
            PACK_F32X2(p1, x1, x1);
            int k = k4 * 4 + j;
#pragma unroll
            for (int q = 0; q < 4; ++q) {
                ulonglong2 w = Ws[k * 4 + q];
                FMA_F32X2(a0[q * 2 + 0], p0, w.x, a0[q * 2 + 0]);
                FMA_F32X2(a0[q * 2 + 1], p0, w.y, a0[q * 2 + 1]);
                FMA_F32X2(a1[q * 2 + 0], p1, w.x, a1[q * 2 + 0]);
                FMA_F32X2(a1[q * 2 + 1], p1, w.y, a1[q * 2 + 1]);
            }
        }
    }

    {
        float d = g_dinv[n0];
        float4* zo = (float4*)&g_z[(size_t)n0 * 16];
#pragma unroll
        for (int q = 0; q < 4; ++q) {
            float e0, e1, e2, e3;
            UNPACK_F32X2(e0, e1, a0[q * 2 + 0]);
            UNPACK_F32X2(e2, e3, a0[q * 2 + 1]);
            zo[q] = make_float4(e0 * d, e1 * d, e2 * d, e3 * d);
        }
    }
    if (n1 < N) {
        float d = g_dinv[n1];
        float4* zo = (float4*)&g_z[(size_t)n1 * 16];
#pragma unroll
        for (int q = 0; q < 4; ++q) {
            float e0, e1, e2, e3;
            UNPACK_F32X2(e0, e1, a1[q * 2 + 0]);
            UNPACK_F32X2(e2, e3, a1[q * 2 + 1]);
            zo[q] = make_float4(e0 * d, e1 * d, e2 * d, e3 * d);
        }
    }
}

// ---------------- Aggregation 1 ----------------
__global__ void agg1_k(const float* __restrict__ b1, int N) {
    int tid = threadIdx.x;
    int gi  = tid >> 2;
    int l   = tid & 3;
    int node = blockIdx.x * 64 + gi;
    if (node >= N) return;

    int beg = g_rowptr[node];
    int end = g_rowptr[node + 1];
    const float4* z4 = (const float4*)g_z;
    float4 acc = make_float4(0.f, 0.f, 0.f, 0.f);
    int p = beg;
    for (; p + 2 <= end; p += 2) {
        int s0 = g_col[p], s1 = g_col[p + 1];
        float4 a = z4[(size_t)s0 * 4 + l];
        float4 b = z4[(size_t)s1 * 4 + l];
        acc.x += a.x + b.x; acc.y += a.y + b.y;
        acc.z += a.z + b.z; acc.w += a.w + b.w;
    }
    if (p < end) {
        float4 a = z4[(size_t)g_col[p] * 4 + l];
        acc.x += a.x; acc.y += a.y; acc.z += a.z; acc.w += a.w;
    }
    float4 self = z4[(size_t)node * 4 + l];
    float di = g_dinv[node];
    float4 bb = ((const float4*)b1)[l];
    float4 o;
    o.x = fmaxf(fmaf(di, acc.x + self.x, bb.x), 0.f);
    o.y = fmaxf(fmaf(di, acc.y + self.y, bb.y), 0.f);
    o.z = fmaxf(fmaf(di, acc.z + self.z, bb.z), 0.f);
    o.w = fmaxf(fmaf(di, acc.w + self.w, bb.w), 0.f);
    ((float4*)g_h)[(size_t)node * 4 + l] = o;
}

// ---------------- 10 hops + final W2 + dinv scale ----------------
__global__ void hops_final_k(const float* __restrict__ Wl, const float* __restrict__ bl,
                             const float* __restrict__ W2, int N) {
    __shared__ float Wls[16 * 16];
    __shared__ float W2s[16 * 8];
    __shared__ float bls[16];
    int tid = threadIdx.x;
    if (tid < 256) Wls[tid] = Wl[tid];
    if (tid < 16 * 8) W2s[tid] = 0.f;
    __syncthreads();
    if (tid < 16 * 7) W2s[(tid / 7) * 8 + (tid % 7)] = W2[tid];
    if (tid < 16) bls[tid] = bl[tid];
    __syncthreads();

    int n = blockIdx.x * blockDim.x + tid;
    if (n >= N) return;

    float h[16];
    const float4* hg = (const float4*)&g_h[(size_t)n * 16];
#pragma unroll
    for (int q = 0; q < 4; ++q) {
        float4 v = hg[q];
        h[q * 4 + 0] = v.x; h[q * 4 + 1] = v.y; h[q * 4 + 2] = v.z; h[q * 4 + 3] = v.w;
    }

    const float4* Wl4 = (const float4*)Wls;
#pragma unroll 1
    for (int it = 0; it < 10; ++it) {
        float nh[16];
#pragma unroll
        for (int o = 0; o < 16; ++o) nh[o] = 0.f;
#pragma unroll
        for (int k = 0; k < 16; ++k) {
            float hv = h[k];
#pragma unroll
            for (int o4 = 0; o4 < 4; ++o4) {
                float4 w = Wl4[k * 4 + o4];
                nh[o4 * 4 + 0] = fmaf(hv, w.x, nh[o4 * 4 + 0]);
                nh[o4 * 4 + 1] = fmaf(hv, w.y, nh[o4 * 4 + 1]);
                nh[o4 * 4 + 2] = fmaf(hv, w.z, nh[o4 * 4 + 2]);
                nh[o4 * 4 + 3] = fmaf(hv, w.w, nh[o4 * 4 + 3]);
            }
        }
#pragma unroll
        for (int o = 0; o < 16; ++o)
            h[o] = 0.1f * fmaxf(nh[o] + bls[o], 0.f) + 0.9f * h[o];
    }

    float u[8];
#pragma unroll
    for (int o = 0; o < 8; ++o) u[o] = 0.f;
#pragma unroll
    for (int k = 0; k < 16; ++k) {
        float hv = h[k];
#pragma unroll
        for (int o = 0; o < 7; ++o)
            u[o] = fmaf(hv, W2s[k * 8 + o], u[o]);
    }
    float d = g_dinv[n];
    float4* ug = (float4*)&g_u[(size_t)n * 8];
    ug[0] = make_float4(u[0] * d, u[1] * d, u[2] * d, u[3] * d);
    ug[1] = make_float4(u[4] * d, u[5] * d, u[6] * d, 0.f);
}

// ---------------- Aggregation 2 + bias + log_softmax ----------------
__global__ void agg2_k(const float* __restrict__ b2, float* __restrict__ out, int N) {
    int tid = threadIdx.x;
    int gi  = tid >> 1;
    int l   = tid & 1;
    int node = blockIdx.x * 128 + gi;
    int nc = (node < N) ? node : (N - 1);

    int beg = g_rowptr[nc];
    int end = g_rowptr[nc + 1];
    const float4* u4 = (const float4*)g_u;
    float4 acc = make_float4(0.f, 0.f, 0.f, 0.f);
    int p = beg;
    for (; p + 2 <= end; p += 2) {
        int s0 = g_col[p], s1 = g_col[p + 1];
        float4 a = u4[(size_t)s0 * 2 + l];
        float4 b = u4[(size_t)s1 * 2 + l];
        acc.x += a.x + b.x; acc.y += a.y + b.y;
        acc.z += a.z + b.z; acc.w += a.w + b.w;
    }
    if (p < end) {
        float4 a = u4[(size_t)g_col[p] * 2 + l];
        acc.x += a.x; acc.y += a.y; acc.z += a.z; acc.w += a.w;
    }
    float4 self = u4[(size_t)nc * 2 + l];
    float di = g_dinv[nc];

    float4 v;
    if (l == 0) {
        v.x = fmaf(di, acc.x + self.x, b2[0]);
        v.y = fmaf(di, acc.y + self.y, b2[1]);
        v.z = fmaf(di, acc.z + self.z, b2[2]);
        v.w = fmaf(di, acc.w + self.w, b2[3]);
    } else {
        v.x = fmaf(di, acc.x + self.x, b2[4]);
        v.y = fmaf(di, acc.y + self.y, b2[5]);
        v.z = fmaf(di, acc.z + self.z, b2[6]);
        v.w = -INFINITY;
    }

    float m = fmaxf(fmaxf(v.x, v.y), fmaxf(v.z, v.w));
    m = fmaxf(m, __shfl_xor_sync(0xFFFFFFFFu, m, 1));
    float ex = __expf(v.x - m) + __expf(v.y - m) + __expf(v.z - m) +
               ((l == 0) ? __expf(v.w - m) : 0.f);
    float s = ex + __shfl_xor_sync(0xFFFFFFFFu, ex, 1);
    float lse = m + __logf(s);

    if (node < N) {
        float* op = out + (size_t)node * 7;
        if (l == 0) {
            op[0] = v.x - lse; op[1] = v.y - lse;
            op[2] = v.z - lse; op[3] = v.w - lse;
        } else {
            op[4] = v.x - lse; op[5] = v.y - lse; op[6] = v.z - lse;
        }
    }
}

// ---------------- launch ----------------
extern "C" void kernel_launch(void* const* d_in, const int* in_sizes, int n_in,
                              void* d_out, int out_size) {
    const float* x  = (const float*)d_in[0];
    const int*   ei = (const int*)d_in[1];
    const float* W1 = (const float*)d_in[2];
    const float* b1 = (const float*)d_in[3];
    const float* Wl = (const float*)d_in[4];
    const float* bl = (const float*)d_in[5];
    const float* W2 = (const float*)d_in[6];
    const float* b2 = (const float*)d_in[7];
    float* out = (float*)d_out;

    int N = in_sizes[0] / 512;
    int E = in_sizes[1] / 2;
    int nb = (N + 1023) / 1024;
    int eb4 = ((E + 3) / 4 + 255) / 256;

    zero_cnt_k<<<(N + 255) / 256, 256>>>(N);
    count_k<<<eb4, 256>>>(ei, E, N);
    partial_k<<<nb, 1024>>>(N);
    scanpart_k<<<1, 128>>>(nb, N);
    emit_k<<<nb, 1024>>>(N);
    scatter_k<<<eb4, 256>>>(ei, E, N);
    gemm1_k<<<(N + 255) / 256, 128>>>(x, W1, N);
    agg1_k<<<(N + 63) / 64, 256>>>(b1, N);
    hops_final_k<<<(N + 255) / 256, 256>>>(Wl, bl, W2, N);
    agg2_k<<<(N + 127) / 128, 256>>>(b2, out, N);
}

// round 5
// speedup vs baseline: 1.0643x; 1.0643x over previous
#include <cuda_runtime.h>
#include <cuda_bf16.h>
#include <math.h>

// ---------------- device scratch (no allocations allowed) ----------------
#define MAXN 100000
#define MAXE 3400000

__device__ int   g_cnt[MAXN];
__device__ int   g_rowptr[MAXN + 1];   // start offsets (not monotonic!)
__device__ int   g_wtmp[MAXN];
__device__ int   g_total;
__device__ int   g_col[MAXE];
__device__ float g_dinv[MAXN];
__device__ float g_z[MAXN * 16];       // UNSCALED x@W1
__device__ float g_h[MAXN * 16];
__device__ float g_u[MAXN * 8];        // dinv-scaled h@W2 (padded to 8)

// packed f32x2 helpers (sm_103a)
#define FMA_F32X2(d, a, b, c) \
    asm("fma.rn.f32x2 %0, %1, %2, %3;" : "=l"(d) : "l"(a), "l"(b), "l"(c))
#define PACK_F32X2(p, lo, hi) \
    asm("mov.b64 %0, {%1, %2};" : "=l"(p) : "f"(lo), "f"(hi))
#define UNPACK_F32X2(lo, hi, p) \
    asm("mov.b64 {%0, %1}, %2;" : "=f"(lo), "=f"(hi) : "l"(p))

// ---------------- CSR build ----------------
__global__ void zero_cnt_k(int N) {
    int i = blockIdx.x * blockDim.x + threadIdx.x;
    if (i < N) g_cnt[i] = 0;
    if (i == 0) g_total = 0;
}

__global__ void count_k(const int* __restrict__ ei, int E, int N) {
    int base = (blockIdx.x * blockDim.x + threadIdx.x) * 4;
    const int* dstp = ei + E;
    if (base + 3 < E) {
        int4 d4 = *(const int4*)&dstp[base];
        if ((unsigned)d4.x < (unsigned)N) atomicAdd(&g_cnt[d4.x], 1);
        if ((unsigned)d4.y < (unsigned)N) atomicAdd(&g_cnt[d4.y], 1);
        if ((unsigned)d4.z < (unsigned)N) atomicAdd(&g_cnt[d4.z], 1);
        if ((unsigned)d4.w < (unsigned)N) atomicAdd(&g_cnt[d4.w], 1);
    } else {
        for (int e = base; e < E; ++e) {
            int d = dstp[e];
            if ((unsigned)d < (unsigned)N) atomicAdd(&g_cnt[d], 1);
        }
    }
}

// one-pass offsets: block scan + atomic block base (CSR = start + count)
__global__ void offsets_k(int N) {
    __shared__ int wsums[32];
    __shared__ int base_sh;
    int tid = threadIdx.x;
    int lane = tid & 31, wid = tid >> 5;
    int i = blockIdx.x * 1024 + tid;
    int c = (i < N) ? g_cnt[i] : 0;
    int v = c;
#pragma unroll
    for (int off = 1; off < 32; off <<= 1) {
        int t = __shfl_up_sync(0xFFFFFFFFu, v, off);
        if (lane >= off) v += t;
    }
    if (lane == 31) wsums[wid] = v;
    __syncthreads();
    if (wid == 0) {
        int w = wsums[lane];
#pragma unroll
        for (int off = 1; off < 32; off <<= 1) {
            int t = __shfl_up_sync(0xFFFFFFFFu, w, off);
            if (lane >= off) w += t;
        }
        wsums[lane] = w;
    }
    __syncthreads();
    if (tid == 0) base_sh = atomicAdd(&g_total, wsums[31]);
    __syncthreads();
    int add = (wid > 0) ? wsums[wid - 1] : 0;
    int start = base_sh + (v - c) + add;
    if (i < N) {
        g_rowptr[i] = start;
        g_wtmp[i]   = start;
        g_dinv[i]   = rsqrtf((float)(c + 1));
    }
}

__global__ void scatter_k(const int* __restrict__ ei, int E, int N) {
    int base = (blockIdx.x * blockDim.x + threadIdx.x) * 4;
    const int* dstp = ei + E;
    if (base + 3 < E) {
        int4 s4 = *(const int4*)&ei[base];
        int4 d4 = *(const int4*)&dstp[base];
        if ((unsigned)d4.x < (unsigned)N && (unsigned)s4.x < (unsigned)N)
            g_col[atomicAdd(&g_wtmp[d4.x], 1)] = s4.x;
        if ((unsigned)d4.y < (unsigned)N && (unsigned)s4.y < (unsigned)N)
            g_col[atomicAdd(&g_wtmp[d4.y], 1)] = s4.y;
        if ((unsigned)d4.z < (unsigned)N && (unsigned)s4.z < (unsigned)N)
            g_col[atomicAdd(&g_wtmp[d4.z], 1)] = s4.z;
        if ((unsigned)d4.w < (unsigned)N && (unsigned)s4.w < (unsigned)N)
            g_col[atomicAdd(&g_wtmp[d4.w], 1)] = s4.w;
    } else {
        for (int e = base; e < E; ++e) {
            int s = ei[e], d = dstp[e];
            if ((unsigned)d < (unsigned)N && (unsigned)s < (unsigned)N)
                g_col[atomicAdd(&g_wtmp[d], 1)] = s;
        }
    }
}

// ---------------- GEMM1: z = x @ W1 (UNSCALED) [N,512]x[512,16] ----------------
// 2 ADJACENT nodes/thread, f32x2 accumulators, 8 front-batched LDG.128 per iter.
__global__ void __launch_bounds__(256) gemm1_k(const float* __restrict__ x,
                                               const float* __restrict__ W1, int N) {
    __shared__ ulonglong2 Ws[512 * 4];   // [k][quad] = 32 KB
    int tid = threadIdx.x;
    {
        const float4* Wg4 = (const float4*)W1;
        float4* Wsf = (float4*)Ws;
        for (int i = tid; i < 2048; i += 256) Wsf[i] = Wg4[i];
    }
    __syncthreads();

    int t  = blockIdx.x * 256 + tid;
    int n0 = t * 2;
    if (n0 >= N) return;
    int n1  = n0 + 1;
    int n1c = (n1 < N) ? n1 : n0;

    const float4* xr0 = (const float4*)(x + (size_t)n0  * 512);
    const float4* xr1 = (const float4*)(x + (size_t)n1c * 512);

    unsigned long long a0[8], a1[8];
#pragma unroll
    for (int p = 0; p < 8; ++p) { a0[p] = 0ull; a1[p] = 0ull; }

    for (int kk = 0; kk < 128; kk += 4) {
        float4 v0[4], v1[4];
#pragma unroll
        for (int u = 0; u < 4; ++u) { v0[u] = xr0[kk + u]; v1[u] = xr1[kk + u]; }
#pragma unroll
        for (int u = 0; u < 4; ++u) {
#pragma unroll
            for (int j = 0; j < 4; ++j) {
                float x0 = (j == 0) ? v0[u].x : (j == 1) ? v0[u].y : (j == 2) ? v0[u].z : v0[u].w;
                float x1 = (j == 0) ? v1[u].x : (j == 1) ? v1[u].y : (j == 2) ? v1[u].z : v1[u].w;
                unsigned long long p0, p1;
                PACK_F32X2(p0, x0, x0);
                PACK_F32X2(p1, x1, x1);
                int k = (kk + u) * 4 + j;
#pragma unroll
                for (int q = 0; q < 4; ++q) {
                    ulonglong2 w = Ws[k * 4 + q];
                    FMA_F32X2(a0[q * 2 + 0], p0, w.x, a0[q * 2 + 0]);
                    FMA_F32X2(a0[q * 2 + 1], p0, w.y, a0[q * 2 + 1]);
                    FMA_F32X2(a1[q * 2 + 0], p1, w.x, a1[q * 2 + 0]);
                    FMA_F32X2(a1[q * 2 + 1], p1, w.y, a1[q * 2 + 1]);
                }
            }
        }
    }

    {
        float4* zo = (float4*)&g_z[(size_t)n0 * 16];
#pragma unroll
        for (int q = 0; q < 4; ++q) {
            float e0, e1, e2, e3;
            UNPACK_F32X2(e0, e1, a0[q * 2 + 0]);
            UNPACK_F32X2(e2, e3, a0[q * 2 + 1]);
            zo[q] = make_float4(e0, e1, e2, e3);
        }
    }
    if (n1 < N) {
        float4* zo = (float4*)&g_z[(size_t)n1 * 16];
#pragma unroll
        for (int q = 0; q < 4; ++q) {
            float e0, e1, e2, e3;
            UNPACK_F32X2(e0, e1, a1[q * 2 + 0]);
            UNPACK_F32X2(e2, e3, a1[q * 2 + 1]);
            zo[q] = make_float4(e0, e1, e2, e3);
        }
    }
}

// ---------------- Aggregation 1 (dinv[src] applied at gather) ----------------
__global__ void agg1_k(const float* __restrict__ b1, int N) {
    int tid = threadIdx.x;
    int gi  = tid >> 2;
    int l   = tid & 3;
    int node = blockIdx.x * 64 + gi;
    if (node >= N) return;

    int beg = g_rowptr[node];
    int end = beg + g_cnt[node];
    const float4* z4 = (const float4*)g_z;
    float4 acc = make_float4(0.f, 0.f, 0.f, 0.f);
    int p = beg;
    for (; p + 2 <= end; p += 2) {
        int s0 = g_col[p], s1 = g_col[p + 1];
        float d0 = g_dinv[s0], d1 = g_dinv[s1];
        float4 a = z4[(size_t)s0 * 4 + l];
        float4 b = z4[(size_t)s1 * 4 + l];
        acc.x = fmaf(d0, a.x, fmaf(d1, b.x, acc.x));
        acc.y = fmaf(d0, a.y, fmaf(d1, b.y, acc.y));
        acc.z = fmaf(d0, a.z, fmaf(d1, b.z, acc.z));
        acc.w = fmaf(d0, a.w, fmaf(d1, b.w, acc.w));
    }
    if (p < end) {
        int s0 = g_col[p];
        float d0 = g_dinv[s0];
        float4 a = z4[(size_t)s0 * 4 + l];
        acc.x = fmaf(d0, a.x, acc.x); acc.y = fmaf(d0, a.y, acc.y);
        acc.z = fmaf(d0, a.z, acc.z); acc.w = fmaf(d0, a.w, acc.w);
    }
    float dn = g_dinv[node];
    float4 self = z4[(size_t)node * 4 + l];
    acc.x = fmaf(dn, self.x, acc.x); acc.y = fmaf(dn, self.y, acc.y);
    acc.z = fmaf(dn, self.z, acc.z); acc.w = fmaf(dn, self.w, acc.w);
    float4 bb = ((const float4*)b1)[l];
    float4 o;
    o.x = fmaxf(fmaf(dn, acc.x, bb.x), 0.f);
    o.y = fmaxf(fmaf(dn, acc.y, bb.y), 0.f);
    o.z = fmaxf(fmaf(dn, acc.z, bb.z), 0.f);
    o.w = fmaxf(fmaf(dn, acc.w, bb.w), 0.f);
    ((float4*)g_h)[(size_t)node * 4 + l] = o;
}

// ---------------- 10 hops + final W2 + dinv scale ----------------
__global__ void hops_final_k(const float* __restrict__ Wl, const float* __restrict__ bl,
                             const float* __restrict__ W2, int N) {
    __shared__ float Wls[16 * 16];
    __shared__ float W2s[16 * 8];
    __shared__ float bls[16];
    int tid = threadIdx.x;
    if (tid < 256) Wls[tid] = Wl[tid];
    if (tid < 16 * 8) W2s[tid] = 0.f;
    __syncthreads();
    if (tid < 16 * 7) W2s[(tid / 7) * 8 + (tid % 7)] = W2[tid];
    if (tid < 16) bls[tid] = bl[tid];
    __syncthreads();

    int n = blockIdx.x * blockDim.x + tid;
    if (n >= N) return;

    float h[16];
    const float4* hg = (const float4*)&g_h[(size_t)n * 16];
#pragma unroll
    for (int q = 0; q < 4; ++q) {
        float4 v = hg[q];
        h[q * 4 + 0] = v.x; h[q * 4 + 1] = v.y; h[q * 4 + 2] = v.z; h[q * 4 + 3] = v.w;
    }

    const float4* Wl4 = (const float4*)Wls;
#pragma unroll 1
    for (int it = 0; it < 10; ++it) {
        float nh[16];
#pragma unroll
        for (int o = 0; o < 16; ++o) nh[o] = 0.f;
#pragma unroll
        for (int k = 0; k < 16; ++k) {
            float hv = h[k];
#pragma unroll
            for (int o4 = 0; o4 < 4; ++o4) {
                float4 w = Wl4[k * 4 + o4];
                nh[o4 * 4 + 0] = fmaf(hv, w.x, nh[o4 * 4 + 0]);
                nh[o4 * 4 + 1] = fmaf(hv, w.y, nh[o4 * 4 + 1]);
                nh[o4 * 4 + 2] = fmaf(hv, w.z, nh[o4 * 4 + 2]);
                nh[o4 * 4 + 3] = fmaf(hv, w.w, nh[o4 * 4 + 3]);
            }
        }
#pragma unroll
        for (int o = 0; o < 16; ++o)
            h[o] = 0.1f * fmaxf(nh[o] + bls[o], 0.f) + 0.9f * h[o];
    }

    float u[8];
#pragma unroll
    for (int o = 0; o < 8; ++o) u[o] = 0.f;
#pragma unroll
    for (int k = 0; k < 16; ++k) {
        float hv = h[k];
#pragma unroll
        for (int o = 0; o < 7; ++o)
            u[o] = fmaf(hv, W2s[k * 8 + o], u[o]);
    }
    float d = g_dinv[n];
    float4* ug = (float4*)&g_u[(size_t)n * 8];
    ug[0] = make_float4(u[0] * d, u[1] * d, u[2] * d, u[3] * d);
    ug[1] = make_float4(u[4] * d, u[5] * d, u[6] * d, 0.f);
}

// ---------------- Aggregation 2 + bias + log_softmax ----------------
__global__ void agg2_k(const float* __restrict__ b2, float* __restrict__ out, int N) {
    int tid = threadIdx.x;
    int gi  = tid >> 1;
    int l   = tid & 1;
    int node = blockIdx.x * 128 + gi;
    int nc = (node < N) ? node : (N - 1);

    int beg = g_rowptr[nc];
    int end = beg + g_cnt[nc];
    const float4* u4 = (const float4*)g_u;
    float4 acc = make_float4(0.f, 0.f, 0.f, 0.f);
    int p = beg;
    for (; p + 2 <= end; p += 2) {
        int s0 = g_col[p], s1 = g_col[p + 1];
        float4 a = u4[(size_t)s0 * 2 + l];
        float4 b = u4[(size_t)s1 * 2 + l];
        acc.x += a.x + b.x; acc.y += a.y + b.y;
        acc.z += a.z + b.z; acc.w += a.w + b.w;
    }
    if (p < end) {
        float4 a = u4[(size_t)g_col[p] * 2 + l];
        acc.x += a.x; acc.y += a.y; acc.z += a.z; acc.w += a.w;
    }
    float4 self = u4[(size_t)nc * 2 + l];
    float di = g_dinv[nc];

    float4 v;
    if (l == 0) {
        v.x = fmaf(di, acc.x + self.x, b2[0]);
        v.y = fmaf(di, acc.y + self.y, b2[1]);
        v.z = fmaf(di, acc.z + self.z, b2[2]);
        v.w = fmaf(di, acc.w + self.w, b2[3]);
    } else {
        v.x = fmaf(di, acc.x + self.x, b2[4]);
        v.y = fmaf(di, acc.y + self.y, b2[5]);
        v.z = fmaf(di, acc.z + self.z, b2[6]);
        v.w = -INFINITY;
    }

    float m = fmaxf(fmaxf(v.x, v.y), fmaxf(v.z, v.w));
    m = fmaxf(m, __shfl_xor_sync(0xFFFFFFFFu, m, 1));
    float ex = __expf(v.x - m) + __expf(v.y - m) + __expf(v.z - m) +
               ((l == 0) ? __expf(v.w - m) : 0.f);
    float s = ex + __shfl_xor_sync(0xFFFFFFFFu, ex, 1);
    float lse = m + __logf(s);

    if (node < N) {
        float* op = out + (size_t)node * 7;
        if (l == 0) {
            op[0] = v.x - lse; op[1] = v.y - lse;
            op[2] = v.z - lse; op[3] = v.w - lse;
        } else {
            op[4] = v.x - lse; op[5] = v.y - lse; op[6] = v.z - lse;
        }
    }
}

// ---------------- launch ----------------
extern "C" void kernel_launch(void* const* d_in, const int* in_sizes, int n_in,
                              void* d_out, int out_size) {
    const float* x  = (const float*)d_in[0];
    const int*   ei = (const int*)d_in[1];
    const float* W1 = (const float*)d_in[2];
    const float* b1 = (const float*)d_in[3];
    const float* Wl = (const float*)d_in[4];
    const float* bl = (const float*)d_in[5];
    const float* W2 = (const float*)d_in[6];
    const float* b2 = (const float*)d_in[7];
    float* out = (float*)d_out;

    int N = in_sizes[0] / 512;
    int E = in_sizes[1] / 2;
    int nb = (N + 1023) / 1024;
    int eb4 = ((E + 3) / 4 + 255) / 256;

    zero_cnt_k<<<(N + 255) / 256, 256>>>(N);
    count_k<<<eb4, 256>>>(ei, E, N);
    offsets_k<<<nb, 1024>>>(N);
    gemm1_k<<<((N + 1) / 2 + 255) / 256, 256>>>(x, W1, N);   // 4th launch -> profiled
    scatter_k<<<eb4, 256>>>(ei, E, N);
    agg1_k<<<(N + 63) / 64, 256>>>(b1, N);
    hops_final_k<<<(N + 255) / 256, 256>>>(Wl, bl, W2, N);
    agg2_k<<<(N + 127) / 128, 256>>>(b2, out, N);
}